// round 6
// baseline (speedup 1.0000x reference)
#include <cuda_runtime.h>
#include <cuda_bf16.h>
#include <math.h>

// Problem constants
#define BATCH   8
#define SEQ     8192
#define DMODEL  256
#define NC      128          // chunks along T
#define CHUNK   (SEQ / NC)   // 64  (multiple of 16 -> aligned to scan blocks)

// Scratch: raw chunk-local complex sums and exclusive chunk prefix (carry-in).
// Layout [(b*NC + c)*DMODEL + d] as float4 = (s0r, s0i, s1r, s1i). 4.2 MB each.
__device__ float4 g_P  [BATCH * NC * DMODEL];
__device__ float4 g_Hin[BATCH * NC * DMODEL];

// ---------------------------------------------------------------------------
// Bit-exact emulation of XLA ReduceWindowRewriter's blocked-rescan cumsum of a
// CONSTANT c (base_length = 16, as on XLA:CPU), vectorized over 4 lanes
// (phase0, phase1, mag0, mag1):
//   inclusive value at n = i+1 terms:
//     r0 = i & 15, q0 = i >> 4
//     V = (q0 == 0) ? seq_{r0+1}(c) : fl( E1(q0) + seq_{r0+1}(c) )
//   E1(q) = inclusive scan of block-total T1 = seq_16(c) at q terms,
//           recursively blocked the same way (levels 512 -> 32 -> 2).
// seq_m(v) = left-to-right fp32 sum of m copies of v (naive window eval).
// Pure fp32 adds; nvcc does not reassociate, and there are no mul+add pairs
// to contract, so rounding matches the reference op-for-op.
// ---------------------------------------------------------------------------
__device__ __forceinline__ float4 f4add(float4 a, float4 b) {
    return make_float4(a.x + b.x, a.y + b.y, a.z + b.z, a.w + b.w);
}

__device__ __forceinline__ float4 seqm(float4 v, int m) {   // m >= 1
    float4 a = v;
    for (int k = 1; k < m; k++) a = f4add(a, v);
    return a;
}

__device__ __forceinline__ float4 computeE1(int q, float4 T1, float4 T2, float4 T3) {
    // inclusive scan of constant T1 at q terms (1 <= q <= 511)
    int j  = q - 1, r1 = j & 15, q1 = j >> 4;        // q1 in [0,31]
    float4 in1 = seqm(T1, r1 + 1);
    if (q1 == 0) return in1;
    int j2 = q1 - 1, r2 = j2 & 15, q2 = j2 >> 4;     // q2 in {0,1}
    float4 in2 = seqm(T2, r2 + 1);
    float4 E2  = q2 ? f4add(T3, in2) : in2;
    return f4add(E2, in1);
}

// Per-(d,t) factors matching the reference tables:
//   descale: (dnr, dni) = exp(-cum_r) * (cos(-cum_i), sin(-cum_i))
//   rescale: (ecr, eci) = exp(+cum_r) * (cos(+cum_i), sin(+cum_i))
struct Fac { float dnr0, dni0, dnr1, dni1, ecr0, eci0, ecr1, eci1; };

__device__ __forceinline__ Fac factors_from_cum(float4 cum) {
    float sn0, cs0, sn1, cs1;
    sincosf(cum.x, &sn0, &cs0);
    sincosf(cum.y, &sn1, &cs1);
    float en0 = expf(-cum.z), ec0 = expf(cum.z);
    float en1 = expf(-cum.w), ec1 = expf(cum.w);
    Fac f;
    f.dnr0 = en0 * cs0;  f.dni0 = -en0 * sn0;
    f.dnr1 = en1 * cs1;  f.dni1 = -en1 * sn1;
    f.ecr0 = ec0 * cs0;  f.eci0 = ec0 * sn0;
    f.ecr1 = ec1 * cs1;  f.eci1 = ec1 * sn1;
    return f;
}

// ---------------------------------------------------------------------------
// K1: chunk-local raw sums S = sum_t descale_t (.) (B * x_t), all 8 batches
// per block so factors are computed once per (d,t). grid = NC, block = DMODEL.
// ---------------------------------------------------------------------------
__global__ __launch_bounds__(DMODEL) void k_partial(
    const float* __restrict__ x,
    const float* __restrict__ aph, const float* __restrict__ lam,
    const float* __restrict__ Br,  const float* __restrict__ Bi)
{
    const int d = threadIdx.x;
    const int c = blockIdx.x;

    const float4 cv = make_float4(aph[2 * d + 0], aph[2 * d + 1],
                                  lam[2 * d + 0], lam[2 * d + 1]);
    const float4 T1 = seqm(cv, 16);
    const float4 T2 = seqm(T1, 16);
    const float4 T3 = seqm(T2, 16);

    const float br0 = Br[2 * d + 0], br1 = Br[2 * d + 1];
    const float bi0 = Bi[2 * d + 0], bi1 = Bi[2 * d + 1];

    float S[BATCH][4];
    #pragma unroll
    for (int b = 0; b < BATCH; b++)
        S[b][0] = S[b][1] = S[b][2] = S[b][3] = 0.f;

    const float* xbase = x + ((size_t)c * CHUNK) * DMODEL + d;

    for (int blk = 0; blk < CHUNK / 16; blk++) {
        const int q0 = c * (CHUNK / 16) + blk;
        float4 E1 = make_float4(0.f, 0.f, 0.f, 0.f);
        if (q0 > 0) E1 = computeE1(q0, T1, T2, T3);
        float4 in0 = cv;

        #pragma unroll
        for (int r0 = 0; r0 < 16; r0++) {
            const int t = blk * 16 + r0;
            if (r0 > 0) in0 = f4add(in0, cv);

            float xv[BATCH];
            #pragma unroll
            for (int b = 0; b < BATCH; b++)
                xv[b] = __ldg(xbase + ((size_t)b * SEQ + t) * DMODEL);

            float4 cum = (q0 == 0) ? in0 : f4add(E1, in0);
            Fac f = factors_from_cum(cum);

            #pragma unroll
            for (int b = 0; b < BATCH; b++) {
                float bur0 = br0 * xv[b], bui0 = bi0 * xv[b];
                float bur1 = br1 * xv[b], bui1 = bi1 * xv[b];
                S[b][0] = fmaf(f.dnr0, bur0, fmaf(-f.dni0, bui0, S[b][0]));
                S[b][1] = fmaf(f.dnr0, bui0, fmaf( f.dni0, bur0, S[b][1]));
                S[b][2] = fmaf(f.dnr1, bur1, fmaf(-f.dni1, bui1, S[b][2]));
                S[b][3] = fmaf(f.dnr1, bui1, fmaf( f.dni1, bur1, S[b][3]));
            }
        }
    }

    #pragma unroll
    for (int b = 0; b < BATCH; b++)
        g_P[((size_t)b * NC + c) * DMODEL + d] =
            make_float4(S[b][0], S[b][1], S[b][2], S[b][3]);
}

// ---------------------------------------------------------------------------
// K2: exclusive prefix SUM over chunks (plain addition — sums are raw).
// 2048 threads, NC=128 iterations, L2-resident data.
// ---------------------------------------------------------------------------
__global__ void k_scan() {
    int idx = blockIdx.x * blockDim.x + threadIdx.x;
    if (idx >= BATCH * DMODEL) return;
    int b = idx >> 8;
    int d = idx & (DMODEL - 1);

    float4 s = make_float4(0.f, 0.f, 0.f, 0.f);
    #pragma unroll 8
    for (int c = 0; c < NC; c++) {
        size_t k = ((size_t)b * NC + c) * DMODEL + d;
        g_Hin[k] = s;
        float4 p = g_P[k];
        s.x += p.x; s.y += p.y; s.z += p.z; s.w += p.w;
    }
}

// ---------------------------------------------------------------------------
// K3: redo local sums seeded with carry, rescale to h, emit y.
// ---------------------------------------------------------------------------
__global__ __launch_bounds__(DMODEL) void k_output(
    const float* __restrict__ x,
    const float* __restrict__ aph, const float* __restrict__ lam,
    const float* __restrict__ Br,  const float* __restrict__ Bi,
    const float* __restrict__ Cr,  const float* __restrict__ Ci,
    const float* __restrict__ Dd,
    float* __restrict__ y)
{
    const int d = threadIdx.x;
    const int c = blockIdx.x;

    const float4 cv = make_float4(aph[2 * d + 0], aph[2 * d + 1],
                                  lam[2 * d + 0], lam[2 * d + 1]);
    const float4 T1 = seqm(cv, 16);
    const float4 T2 = seqm(T1, 16);
    const float4 T3 = seqm(T2, 16);

    const float br0 = Br[2 * d + 0], br1 = Br[2 * d + 1];
    const float bi0 = Bi[2 * d + 0], bi1 = Bi[2 * d + 1];
    const float cr0 = Cr[2 * d + 0], cr1 = Cr[2 * d + 1];
    const float ci0 = Ci[2 * d + 0], ci1 = Ci[2 * d + 1];
    const float dd  = Dd[d];

    float S[BATCH][4];
    #pragma unroll
    for (int b = 0; b < BATCH; b++) {
        float4 h = g_Hin[((size_t)b * NC + c) * DMODEL + d];
        S[b][0] = h.x; S[b][1] = h.y; S[b][2] = h.z; S[b][3] = h.w;
    }

    const size_t base = ((size_t)c * CHUNK) * DMODEL + d;
    const float* xbase = x + base;
    float*       ybase = y + base;

    for (int blk = 0; blk < CHUNK / 16; blk++) {
        const int q0 = c * (CHUNK / 16) + blk;
        float4 E1 = make_float4(0.f, 0.f, 0.f, 0.f);
        if (q0 > 0) E1 = computeE1(q0, T1, T2, T3);
        float4 in0 = cv;

        #pragma unroll
        for (int r0 = 0; r0 < 16; r0++) {
            const int t = blk * 16 + r0;
            if (r0 > 0) in0 = f4add(in0, cv);

            float xv[BATCH];
            #pragma unroll
            for (int b = 0; b < BATCH; b++)
                xv[b] = __ldg(xbase + ((size_t)b * SEQ + t) * DMODEL);

            float4 cum = (q0 == 0) ? in0 : f4add(E1, in0);
            Fac f = factors_from_cum(cum);

            #pragma unroll
            for (int b = 0; b < BATCH; b++) {
                float bur0 = br0 * xv[b], bui0 = bi0 * xv[b];
                float bur1 = br1 * xv[b], bui1 = bi1 * xv[b];
                S[b][0] = fmaf(f.dnr0, bur0, fmaf(-f.dni0, bui0, S[b][0]));
                S[b][1] = fmaf(f.dnr0, bui0, fmaf( f.dni0, bur0, S[b][1]));
                S[b][2] = fmaf(f.dnr1, bur1, fmaf(-f.dni1, bui1, S[b][2]));
                S[b][3] = fmaf(f.dnr1, bui1, fmaf( f.dni1, bur1, S[b][3]));

                // rescale: h = ec (.) S   (inclusive — after adding term t)
                float h0r = f.ecr0 * S[b][0] - f.eci0 * S[b][1];
                float h0i = f.ecr0 * S[b][1] + f.eci0 * S[b][0];
                float h1r = f.ecr1 * S[b][2] - f.eci1 * S[b][3];
                float h1i = f.ecr1 * S[b][3] + f.eci1 * S[b][2];

                float yv = fmaf(dd, xv[b],
                           fmaf(cr0, h0r, fmaf(-ci0, h0i,
                           fmaf(cr1, h1r, -ci1 * h1i))));
                __stcs(ybase + ((size_t)b * SEQ + t) * DMODEL, yv);
            }
        }
    }
}

// ---------------------------------------------------------------------------
extern "C" void kernel_launch(void* const* d_in, const int* in_sizes, int n_in,
                              void* d_out, int out_size)
{
    (void)in_sizes; (void)n_in; (void)out_size;
    const float* x   = (const float*)d_in[0];
    const float* lam = (const float*)d_in[1];
    const float* aph = (const float*)d_in[2];
    const float* Br  = (const float*)d_in[3];
    const float* Bi  = (const float*)d_in[4];
    const float* Cr  = (const float*)d_in[5];
    const float* Ci  = (const float*)d_in[6];
    const float* Dd  = (const float*)d_in[7];
    float* y = (float*)d_out;

    k_partial<<<NC, DMODEL>>>(x, aph, lam, Br, Bi);
    k_scan<<<(BATCH * DMODEL + 255) / 256, 256>>>();
    k_output<<<NC, DMODEL>>>(x, aph, lam, Br, Bi, Cr, Ci, Dd, y);
}